// round 2
// baseline (speedup 1.0000x reference)
#include <cuda_runtime.h>

// out[n, k=9*i+j, h, w] = sum_z A[n,z,h,w] * B[n,z, h+j-4, w+i-4]  (zero pad)
// N=8, Z=128, H=W=160.
//
// CTA tile: TW=32 x TH=4, all 81 k. Threads (tx=8, h=4, j=9) = 288, warp == one j.
// Each thread: 4 consecutive pixels (w = w0+4*tx), 9 i-shifts, 1 j -> 36 acc.
// All smem traffic is conflict-free LDS.128 (each 8-lane phase reads 128
// contiguous bytes of a single row).

#define N_  8
#define Z_  128
#define H_  160
#define W_  160
#define TW  32
#define TH  4
#define ZC  16
#define NTHREADS 288

__global__ __launch_bounds__(NTHREADS, 3)
void corr_kernel(const float* __restrict__ A,
                 const float* __restrict__ B,
                 float* __restrict__ out)
{
    __shared__ float As[ZC][TH][TW];          // 8 KB
    __shared__ float Bs[ZC][TH + 8][TW + 8];  // 30 KB, rows of 40 floats (160B, 16B-aligned)

    const int tid = threadIdx.x;
    const int tx = tid & 7;          // 0..7  -> w = w0 + 4*tx .. +3
    const int h  = (tid >> 3) & 3;   // 0..3
    const int j  = tid >> 5;         // 0..8  (warp index)

    const int w0 = blockIdx.x * TW;
    const int h0 = blockIdx.y * TH;
    const int n  = blockIdx.z;

    const size_t plane = (size_t)H_ * W_;
    const float* Abase = A + (size_t)n * Z_ * plane;
    const float* Bbase = B + (size_t)n * Z_ * plane;

    float acc[9][4];
    #pragma unroll
    for (int i = 0; i < 9; i++)
        #pragma unroll
        for (int px = 0; px < 4; px++)
            acc[i][px] = 0.0f;

    for (int zc = 0; zc < Z_; zc += ZC) {
        __syncthreads();

        // ---- fill A: ZC*4*32 floats = 512 float4, coalesced ----
        #pragma unroll 1
        for (int idx = tid; idx < ZC * TH * TW / 4; idx += NTHREADS) {
            int z   = idx >> 5;        // 32 float4 per z-slice
            int rem = idx & 31;
            int r   = rem >> 3;
            int c4  = rem & 7;
            float4 v = *(const float4*)(Abase + (size_t)(zc + z) * plane
                                        + (size_t)(h0 + r) * W_ + w0 + c4 * 4);
            ((float4*)As)[idx] = v;
        }

        // ---- fill B: ZC*12*40 floats, zero-padded ----
        #pragma unroll 1
        for (int idx = tid; idx < ZC * (TH + 8) * (TW + 8); idx += NTHREADS) {
            int z   = idx / 480;
            int rem = idx - z * 480;
            int r   = rem / 40;
            int c   = rem - r * 40;
            int gh = h0 - 4 + r;
            int gw = w0 - 4 + c;
            float v = 0.0f;
            if ((unsigned)gh < H_ && (unsigned)gw < W_)
                v = Bbase[(size_t)(zc + z) * plane + (size_t)gh * W_ + gw];
            ((float*)Bs)[idx] = v;
        }
        __syncthreads();

        // ---- compute: per z, 4 LDS.128 + 36 FMA per thread ----
        #pragma unroll 4
        for (int z = 0; z < ZC; z++) {
            float4 av = *(const float4*)&As[z][h][4 * tx];
            float4 b0 = *(const float4*)&Bs[z][h + j][4 * tx];
            float4 b1 = *(const float4*)&Bs[z][h + j][4 * tx + 4];
            float4 b2 = *(const float4*)&Bs[z][h + j][4 * tx + 8];

            float a[4] = {av.x, av.y, av.z, av.w};
            float b[12] = {b0.x, b0.y, b0.z, b0.w,
                           b1.x, b1.y, b1.z, b1.w,
                           b2.x, b2.y, b2.z, b2.w};

            #pragma unroll
            for (int i = 0; i < 9; i++)
                #pragma unroll
                for (int px = 0; px < 4; px++)
                    acc[i][px] += a[px] * b[px + i];
        }
    }

    // ---- store: 9 x STG.128 per thread ----
    float* obase = out + (((size_t)n * 81 + j) * H_ + (h0 + h)) * W_ + w0 + 4 * tx;
    #pragma unroll
    for (int i = 0; i < 9; i++) {
        *(float4*)(obase + (size_t)i * 9 * plane) =
            make_float4(acc[i][0], acc[i][1], acc[i][2], acc[i][3]);
    }
}

extern "C" void kernel_launch(void* const* d_in, const int* in_sizes, int n_in,
                              void* d_out, int out_size)
{
    const float* imgA = (const float*)d_in[0];
    const float* imgB = (const float*)d_in[1];
    float* out = (float*)d_out;

    dim3 grid(W_ / TW, H_ / TH, N_);
    corr_kernel<<<grid, NTHREADS>>>(imgA, imgB, out);
}

// round 4
// speedup vs baseline: 3.0703x; 3.0703x over previous
#include <cuda_runtime.h>

// out[n, k=9*i+j, h, w] = sum_z A[n,z,h,w] * B[n,z, h+j-4, w+i-4]  (zero pad)
// N=8, Z=128, H=W=160.
//
// CTA tile TW=32 x TH=4, threads (tx=8, h=4, j=9)=288, warp == one j.
// Thread: 4 consecutive pixels, 9 i-shifts -> 36 acc. All smem ops LDS.128.
// ZC=8 z-chunk, software-pipelined gmem->reg->smem with fixed fill roles.

#define N_  8
#define Z_  128
#define H_  160
#define W_  160
#define TW  32
#define TH  4
#define ZC  8
#define NCHUNK (Z_ / ZC)     // 16
#define BR  12               // TH + 8
#define BC  48               // 12 float4, covers gw in [w0-8, w0+40)
#define NTHREADS 288

__global__ __launch_bounds__(NTHREADS, 2)
void corr_kernel(const float* __restrict__ A,
                 const float* __restrict__ B,
                 float* __restrict__ out)
{
    __shared__ float As[ZC][TH][TW];   // 4 KB
    __shared__ float Bs[ZC][BR][BC];   // 18 KB

    const int tid = threadIdx.x;
    const int tx = tid & 7;          // w = w0 + 4*tx .. +3
    const int h  = (tid >> 3) & 3;
    const int j  = tid >> 5;         // warp index

    const int w0 = blockIdx.x * TW;
    const int h0 = blockIdx.y * TH;
    const int n  = blockIdx.z;

    const size_t plane = (size_t)H_ * W_;
    const float* Abase = A + (size_t)n * Z_ * plane;
    const float* Bbase = B + (size_t)n * Z_ * plane;

    // ---- fixed B-fill role: per chunk, 12 rows x 12 float4 x ZC z = 1152 f4.
    // thread handles f4 idx = tid + s*288 (s=0..3) -> z = bz0 + 2*s, fixed (r,c).
    const int bz0  = tid / 144;            // 0 or 1
    const int brem = tid - bz0 * 144;
    const int br   = brem / 12;
    const int bc   = brem - br * 12;
    const int bgh  = h0 - 4 + br;
    const int bgw  = w0 - 8 + 4 * bc;
    const bool bvalid = ((unsigned)bgh < H_) && ((unsigned)bgw <= (W_ - 4));
    const float* bptr = Bbase + (size_t)bz0 * plane + (size_t)bgh * W_ + bgw;

    // ---- fixed A-fill role: 256 f4 per chunk, threads tid<256.
    const bool aactive = tid < 256;
    const int az = tid >> 5;
    const int ar = (tid >> 3) & 3;
    const int ac = tid & 7;
    const float* aptr = Abase + (size_t)az * plane + (size_t)(h0 + ar) * W_ + w0 + 4 * ac;

    float4 Bv[4];
    float4 Av = make_float4(0.f, 0.f, 0.f, 0.f);

    // prefetch chunk 0
    #pragma unroll
    for (int s = 0; s < 4; s++)
        Bv[s] = bvalid ? *(const float4*)(bptr + (size_t)(2 * s) * plane)
                       : make_float4(0.f, 0.f, 0.f, 0.f);
    if (aactive) Av = *(const float4*)aptr;

    float acc[9][4];
    #pragma unroll
    for (int i = 0; i < 9; i++)
        #pragma unroll
        for (int px = 0; px < 4; px++)
            acc[i][px] = 0.0f;

    for (int ch = 0; ch < NCHUNK; ch++) {
        __syncthreads();   // previous chunk fully consumed

        // commit staged registers to smem
        #pragma unroll
        for (int s = 0; s < 4; s++)
            *(float4*)&Bs[bz0 + 2 * s][br][4 * bc] = Bv[s];
        if (aactive) *(float4*)&As[az][ar][4 * ac] = Av;

        __syncthreads();

        // prefetch next chunk (LDG latency hidden under compute below)
        if (ch + 1 < NCHUNK) {
            const size_t zoff = (size_t)(ch + 1) * ZC * plane;
            #pragma unroll
            for (int s = 0; s < 4; s++)
                Bv[s] = bvalid ? *(const float4*)(bptr + zoff + (size_t)(2 * s) * plane)
                               : make_float4(0.f, 0.f, 0.f, 0.f);
            if (aactive) Av = *(const float4*)(aptr + zoff);
        }

        // compute: per z, 4x LDS.128 + 36 FFMA (immediate smem offsets)
        #pragma unroll
        for (int z = 0; z < ZC; z++) {
            const float4 av = *(const float4*)&As[z][h][4 * tx];
            const float4 b0 = *(const float4*)&Bs[z][h + j][4 * tx + 4];
            const float4 b1 = *(const float4*)&Bs[z][h + j][4 * tx + 8];
            const float4 b2 = *(const float4*)&Bs[z][h + j][4 * tx + 12];

            const float a0 = av.x, a1 = av.y, a2 = av.z, a3 = av.w;
            const float b[12] = {b0.x, b0.y, b0.z, b0.w,
                                 b1.x, b1.y, b1.z, b1.w,
                                 b2.x, b2.y, b2.z, b2.w};

            #pragma unroll
            for (int i = 0; i < 9; i++) {
                acc[i][0] += a0 * b[i];
                acc[i][1] += a1 * b[i + 1];
                acc[i][2] += a2 * b[i + 2];
                acc[i][3] += a3 * b[i + 3];
            }
        }
    }

    // ---- store: 9 x STG.128
    float* obase = out + (((size_t)n * 81 + j) * H_ + (h0 + h)) * W_ + w0 + 4 * tx;
    #pragma unroll
    for (int i = 0; i < 9; i++)
        *(float4*)(obase + (size_t)i * 9 * plane) =
            make_float4(acc[i][0], acc[i][1], acc[i][2], acc[i][3]);
}

extern "C" void kernel_launch(void* const* d_in, const int* in_sizes, int n_in,
                              void* d_out, int out_size)
{
    const float* imgA = (const float*)d_in[0];
    const float* imgB = (const float*)d_in[1];
    float* out = (float*)d_out;

    dim3 grid(W_ / TW, H_ / TH, N_);
    corr_kernel<<<grid, NTHREADS>>>(imgA, imgB, out);
}

// round 5
// speedup vs baseline: 3.5320x; 1.1504x over previous
#include <cuda_runtime.h>

// out[n, k=9*i+j, h, w] = sum_z A[n,z,h,w] * B[n,z, h+j-4, w+i-4]  (zero pad)
// N=8, Z=128, H=W=160.
//
// CTA tile TW=32 x TH=8. Threads (tx=4, h=8, j=9) = 288; warp == one j.
// Thread: 8 consecutive pixels (w = w0+8*tx), one row, 9 i-shifts -> 72 acc.
// ZC=4 z-chunks, double-buffered smem filled by cp.async.cg (zfill for halo).
// Smem row pads (A:36, B:44 floats) make all LDS.128 phases bank-disjoint.

#define N_  8
#define Z_  128
#define H_  160
#define W_  160
#define TW  32
#define TH  8
#define ZC  4
#define NCH (Z_ / ZC)     // 32
#define AROW 36
#define BROW 44
#define BRN  16           // TH + 8
#define NT  288

__global__ __launch_bounds__(NT, 2)
void corr_kernel(const float* __restrict__ A,
                 const float* __restrict__ B,
                 float* __restrict__ out)
{
    __shared__ float As[2][ZC][TH][AROW];   // 2 * 4.5 KB
    __shared__ float Bs[2][ZC][BRN][BROW];  // 2 * 11 KB

    const int tid = threadIdx.x;
    const int tx = tid & 3;          // w = w0 + 8*tx .. +7
    const int h  = (tid >> 2) & 7;
    const int j  = tid >> 5;         // warp index

    const int w0 = blockIdx.x * TW;
    const int h0 = blockIdx.y * TH;
    const int n  = blockIdx.z;

    const size_t plane = (size_t)H_ * W_;
    const float* Abase = A + (size_t)n * Z_ * plane;
    const float* Bbase = B + (size_t)n * Z_ * plane;

    // ------- fixed fill roles (computed once) -------
    // B: ZC*16*10 = 640 float4/chunk, slots s=0..2 (idx = tid + 288*s)
    unsigned boff[3];     // element offset into Bbase (0 if invalid)
    unsigned bsm[3];      // smem byte addr in buffer 0
    int      bsz[3];      // cp.async src-size: 16 valid, 0 zero-fill
    bool     bact[3];
    #pragma unroll
    for (int s = 0; s < 3; s++) {
        int idx = tid + s * NT;
        bool act = idx < ZC * BRN * 10;
        int ii = act ? idx : 0;
        int z = ii / 160;
        int rem = ii - z * 160;
        int r = rem / 10;
        int c = rem - r * 10;
        int gh = h0 - 4 + r;
        int gw = w0 - 4 + 4 * c;
        bool v = ((unsigned)gh < H_) && ((unsigned)gw <= (W_ - 4));
        bact[s] = act;
        bsz[s] = v ? 16 : 0;
        boff[s] = v ? (unsigned)(z * plane + gh * W_ + gw) : 0u;
        bsm[s] = (unsigned)__cvta_generic_to_shared(&Bs[0][z][r][4 * c]);
    }
    // A: ZC*8*8 = 256 float4/chunk, one slot (tid < 256)
    const bool aact = tid < ZC * TH * 8;
    {
        // placeholder scope
    }
    int ai = aact ? tid : 0;
    int az = ai >> 6;
    int ar = (ai >> 3) & 7;
    int ac = ai & 7;
    const unsigned aoff = (unsigned)(az * plane + (h0 + ar) * W_ + w0 + 4 * ac);
    const unsigned asm0 = (unsigned)__cvta_generic_to_shared(&As[0][az][ar][4 * ac]);

    const unsigned BUFB = (unsigned)sizeof(Bs[0]);
    const unsigned BUFA = (unsigned)sizeof(As[0]);

    float acc[9][8];
    #pragma unroll
    for (int i = 0; i < 9; i++)
        #pragma unroll
        for (int p = 0; p < 8; p++)
            acc[i][p] = 0.0f;

    // ------- issue fills for one chunk -------
    auto issue = [&](int chunk) {
        const int buf = chunk & 1;
        const float* bsrc = Bbase + (size_t)chunk * ZC * plane;
        const float* asrc = Abase + (size_t)chunk * ZC * plane;
        const unsigned bo = buf ? BUFB : 0u;
        const unsigned ao = buf ? BUFA : 0u;
        #pragma unroll
        for (int s = 0; s < 3; s++) {
            if (bact[s]) {
                asm volatile("cp.async.cg.shared.global [%0], [%1], 16, %2;"
                             :: "r"(bsm[s] + bo), "l"(bsrc + boff[s]), "r"(bsz[s]));
            }
        }
        if (aact) {
            asm volatile("cp.async.cg.shared.global [%0], [%1], 16, 16;"
                         :: "r"(asm0 + ao), "l"(asrc + aoff));
        }
        asm volatile("cp.async.commit_group;");
    };

    // ------- prologue: 2 chunks in flight -------
    issue(0);
    issue(1);

    for (int ch = 0; ch < NCH; ch++) {
        if (ch < NCH - 1) asm volatile("cp.async.wait_group 1;");
        else              asm volatile("cp.async.wait_group 0;");
        __syncthreads();

        const int buf = ch & 1;
        #pragma unroll
        for (int z = 0; z < ZC; z++) {
            const float4* ar4 = (const float4*)&As[buf][z][h][8 * tx];
            const float4 a0 = ar4[0];
            const float4 a1 = ar4[1];
            const float4* br4 = (const float4*)&Bs[buf][z][h + j][8 * tx];
            const float4 b0 = br4[0];
            const float4 b1 = br4[1];
            const float4 b2 = br4[2];
            const float4 b3 = br4[3];

            const float a[8] = {a0.x, a0.y, a0.z, a0.w, a1.x, a1.y, a1.z, a1.w};
            const float b[16] = {b0.x, b0.y, b0.z, b0.w, b1.x, b1.y, b1.z, b1.w,
                                 b2.x, b2.y, b2.z, b2.w, b3.x, b3.y, b3.z, b3.w};

            #pragma unroll
            for (int i = 0; i < 9; i++)
                #pragma unroll
                for (int p = 0; p < 8; p++)
                    acc[i][p] += a[p] * b[p + i];
        }
        __syncthreads();   // buffer fully consumed by ALL warps before refill

        if (ch + 2 < NCH) issue(ch + 2);
    }

    // ------- store: 18 x STG.128 -------
    float* ob = out + (((size_t)n * 81 + j) * H_ + (h0 + h)) * W_ + w0 + 8 * tx;
    #pragma unroll
    for (int i = 0; i < 9; i++) {
        *(float4*)(ob + (size_t)(9 * i) * plane) =
            make_float4(acc[i][0], acc[i][1], acc[i][2], acc[i][3]);
        *(float4*)(ob + (size_t)(9 * i) * plane + 4) =
            make_float4(acc[i][4], acc[i][5], acc[i][6], acc[i][7]);
    }
}

extern "C" void kernel_launch(void* const* d_in, const int* in_sizes, int n_in,
                              void* d_out, int out_size)
{
    const float* imgA = (const float*)d_in[0];
    const float* imgB = (const float*)d_in[1];
    float* out = (float*)d_out;

    dim3 grid(W_ / TW, H_ / TH, N_);
    corr_kernel<<<grid, NT>>>(imgA, imgB, out);
}